// round 7
// baseline (speedup 1.0000x reference)
#include <cuda_runtime.h>

// HCEN forward, fully fused persistent kernel:
//   out = (mean_S(x) @ W_enc^T + b_enc) @ W_out^T + b_out
// x[16,4096,1024] f32 (256 MB read, ~32us HBM floor).
// 592 blocks x 256 thr, __launch_bounds__(256,4): 4 CTAs/SM resident on 148
// SMs (also fits 152-SM GB300) -> device-wide spin barriers are safe and the
// x-stream phase has ~32 warps/SM (R6 had 14 -> only 4.9 TB/s).
// x work is 1024 fixed 64-row chunks handed out by an atomic ticket
// (deterministic: each chunk writes its own slot; summation orders fixed).

#define BATCH 16
#define SEQ   4096
#define DIM   1024
#define FB    592               // persistent grid size (<= 4 per SM)
#define NCH   1024              // x chunks
#define CROWS 64                // rows per chunk (64 * 1024 * 4B = 256 KB)

// Device-global scratch (no allocation allowed).
__device__ float g_partials[NCH * DIM];  // 4 MB (per-chunk partial sums)
__device__ float g_m[BATCH * DIM];       // 64 KB
__device__ float g_enc[BATCH * DIM];     // 64 KB
__device__ volatile unsigned g_bar[3];   // zero-init; self-resetting
__device__ unsigned g_chunk;             // work-stealing ticket
__device__ unsigned g_exit;

__device__ __forceinline__ void grid_barrier(int which) {
    __syncthreads();
    if (threadIdx.x == 0) {
        __threadfence();
        atomicAdd((unsigned*)&g_bar[which], 1u);
        while (g_bar[which] < FB) { }
        __threadfence();
    }
    __syncthreads();
}

__global__ void __launch_bounds__(256, 4)
hcen_fused_kernel(const float* __restrict__ x,
                  const float* __restrict__ Wenc,
                  const float* __restrict__ benc,
                  const float* __restrict__ Wout,
                  const float* __restrict__ bout,
                  float* __restrict__ dout) {
    __shared__ float4 smA[4 * (DIM / 4)];   // 16 KB: GEMM A tile / reduce buffer
    __shared__ unsigned sh_c;

    const int t    = threadIdx.x;
    const int w    = t >> 5;
    const int lane = t & 31;
    const int bid  = blockIdx.x;

    // ---- (X) stream x: work-stealing over 1024 chunks of 64 rows. ----
    // Chunk c covers batch b = c>>6, rows [ (c&63)*64, +64 ). Each thread
    // owns float4 column t. __ldcs: read-once, evict-first (protects W in L2).
    for (;;) {
        if (t == 0) sh_c = atomicAdd(&g_chunk, 1u);
        __syncthreads();
        const unsigned c = sh_c;
        __syncthreads();
        if (c >= NCH) break;

        const float4* __restrict__ x4 =
            reinterpret_cast<const float4*>(x) + (size_t)c * CROWS * (DIM / 4);
        float4 acc = make_float4(0.f, 0.f, 0.f, 0.f);
#pragma unroll 8
        for (int s = 0; s < CROWS; s++) {
            float4 v = __ldcs(&x4[(size_t)s * (DIM / 4) + t]);
            acc.x += v.x; acc.y += v.y; acc.z += v.z; acc.w += v.w;
        }
        reinterpret_cast<float4*>(g_partials)[(size_t)c * (DIM / 4) + t] = acc;
    }

    grid_barrier(0);

    // ---- (R) reduce 64 chunk-partials per batch -> mean. Blocks 0..127. ----
    if (bid < 128) {
        const int b   = bid >> 3;          // batch
        const int q   = bid & 7;           // 32-float4 column group
        const int col = t & 31;
        const int cg  = t >> 5;            // 8 chunk-groups of 8
        const float4* __restrict__ p4 = reinterpret_cast<const float4*>(g_partials);

        float4 acc = make_float4(0.f, 0.f, 0.f, 0.f);
#pragma unroll
        for (int i = 0; i < 8; i++) {
            const int k = cg * 8 + i;      // chunk-within-batch 0..63
            float4 v = p4[(size_t)(b * 64 + k) * (DIM / 4) + q * 32 + col];
            acc.x += v.x; acc.y += v.y; acc.z += v.z; acc.w += v.w;
        }
        smA[t] = acc;
        __syncthreads();
        if (t < 32) {
            float4 r = make_float4(0.f, 0.f, 0.f, 0.f);
#pragma unroll
            for (int g = 0; g < 8; g++) {
                float4 v = smA[t + g * 32];
                r.x += v.x; r.y += v.y; r.z += v.z; r.w += v.w;
            }
            const float inv = 1.0f / (float)SEQ;
            r.x *= inv; r.y *= inv; r.z *= inv; r.w *= inv;
            reinterpret_cast<float4*>(g_m)[(size_t)b * (DIM / 4) + q * 32 + t] = r;
        }
    }

    grid_barrier(1);

    // ---- GEMM decomposition: blocks 0..511 active. ----
    // hg = bid>>2 (128 groups of 8 h), qb = bid&3 (batch quarter, 4 batches).
    // Warp w owns h = hg*8 + w, full K=1024 via 8 reg-float4 W loads.
    const int hg = bid >> 2;
    const int qb = bid & 3;
    const int h  = hg * 8 + w;

    // ---- (G1) enc = m @ Wenc^T + benc ----
    if (bid < 512) {
        const float4* __restrict__ M4 = reinterpret_cast<const float4*>(g_m);
#pragma unroll
        for (int i = 0; i < 4; i++)
            smA[t + i * 256] = M4[(size_t)qb * 1024 + t + i * 256];
        __syncthreads();

        const float4* __restrict__ W4 = reinterpret_cast<const float4*>(Wenc) + (size_t)h * (DIM / 4);
        float4 wr[8];
#pragma unroll
        for (int i = 0; i < 8; i++)
            wr[i] = W4[lane + i * 32];

        float acc[4] = {0.f, 0.f, 0.f, 0.f};
#pragma unroll
        for (int i = 0; i < 8; i++) {
            const int j = lane + i * 32;
#pragma unroll
            for (int b = 0; b < 4; b++) {
                const float4 a = smA[b * 256 + j];
                acc[b] += wr[i].x * a.x + wr[i].y * a.y + wr[i].z * a.z + wr[i].w * a.w;
            }
        }
#pragma unroll
        for (int off = 16; off > 0; off >>= 1)
#pragma unroll
            for (int b = 0; b < 4; b++)
                acc[b] += __shfl_down_sync(0xffffffffu, acc[b], off);
        if (lane == 0) {
            const float bv = benc[h];
#pragma unroll
            for (int b = 0; b < 4; b++)
                g_enc[(size_t)(qb * 4 + b) * DIM + h] = acc[b] + bv;
        }
    }

    grid_barrier(2);

    // ---- (G2) out = enc @ Wout^T + bout ----
    if (bid < 512) {
        const float4* __restrict__ E4 = reinterpret_cast<const float4*>(g_enc);
#pragma unroll
        for (int i = 0; i < 4; i++)
            smA[t + i * 256] = E4[(size_t)qb * 1024 + t + i * 256];
        __syncthreads();

        const float4* __restrict__ W4 = reinterpret_cast<const float4*>(Wout) + (size_t)h * (DIM / 4);
        float4 wr[8];
#pragma unroll
        for (int i = 0; i < 8; i++)
            wr[i] = W4[lane + i * 32];

        float acc[4] = {0.f, 0.f, 0.f, 0.f};
#pragma unroll
        for (int i = 0; i < 8; i++) {
            const int j = lane + i * 32;
#pragma unroll
            for (int b = 0; b < 4; b++) {
                const float4 a = smA[b * 256 + j];
                acc[b] += wr[i].x * a.x + wr[i].y * a.y + wr[i].z * a.z + wr[i].w * a.w;
            }
        }
#pragma unroll
        for (int off = 16; off > 0; off >>= 1)
#pragma unroll
            for (int b = 0; b < 4; b++)
                acc[b] += __shfl_down_sync(0xffffffffu, acc[b], off);
        if (lane == 0) {
            const float bv = bout[h];
#pragma unroll
            for (int b = 0; b < 4; b++)
                dout[(size_t)(qb * 4 + b) * DIM + h] = acc[b] + bv;
        }
    }

    // ---- reset counters for next graph replay (last block out). ----
    __syncthreads();
    if (t == 0) {
        unsigned old = atomicAdd(&g_exit, 1u);
        if (old == FB - 1) {
            g_bar[0] = 0;
            g_bar[1] = 0;
            g_bar[2] = 0;
            g_chunk  = 0;
            __threadfence();
            g_exit = 0;
        }
    }
}

extern "C" void kernel_launch(void* const* d_in, const int* in_sizes, int n_in,
                              void* d_out, int out_size) {
    const float* x     = (const float*)d_in[0];
    const float* W_enc = (const float*)d_in[1];
    const float* b_enc = (const float*)d_in[2];
    const float* W_out = (const float*)d_in[3];
    const float* b_out = (const float*)d_in[4];
    float* out = (float*)d_out;

    (void)in_sizes; (void)n_in; (void)out_size;

    hcen_fused_kernel<<<FB, 256>>>(x, W_enc, b_enc, W_out, b_out, out);
}

// round 8
// speedup vs baseline: 1.0398x; 1.0398x over previous
#include <cuda_runtime.h>

// HCEN forward, two kernels:
//  K1: x partial-sum stream (proven 7.2 TB/s shape) + L2 prefetch of both W
//      matrices overlapped with the 35us stream.
//  K2: persistent fused tail (reduce -> GEMM1 -> GEMM2) with device barriers;
//      512 blocks @ 4/SM co-resident, W reads hit L2.

#define BATCH 16
#define SEQ   4096
#define DIM   1024
#define NCHUNK 64
#define SCHUNK (SEQ / NCHUNK)   // 64
#define FB2   512               // tail grid (co-resident at 4/SM)

// Device-global scratch (no allocation allowed).
__device__ float g_partials[NCHUNK * BATCH * DIM];   // 4 MB
__device__ float g_m[BATCH * DIM];                   // 64 KB
__device__ float g_enc[BATCH * DIM];                 // 64 KB
__device__ volatile unsigned g_bar[2];               // zero-init; self-resetting
__device__ unsigned g_exit;

// ---------------------------------------------------------------------------
// K1: partial sums over S-chunks + W L2-prefetch. grid (16, 64), block 256.
// Block (b, c): batch b, rows [c*64, c*64+64). Fully coalesced float4 loads,
// __ldcs (read-once, evict-first). Linear id bl = b*64+c also prefetches an
// 8 KB slice of Wenc (bl<512) or Wout (bl>=512): 1024 blocks x 8 KB = 8 MB.
// ---------------------------------------------------------------------------
__global__ void mean_partial_kernel(const float* __restrict__ x,
                                    const float* __restrict__ Wenc,
                                    const float* __restrict__ Wout) {
    const int b = blockIdx.x;
    const int c = blockIdx.y;
    const int t = threadIdx.x;

    // W prefetch: 64 lines of 128 B per block, issued before the stream.
    {
        const int bl = b * NCHUNK + c;                 // 0..1023
        if (t < 64) {
            const char* base = (bl < 512) ? reinterpret_cast<const char*>(Wenc)
                                          : reinterpret_cast<const char*>(Wout);
            const char* wp = base + (size_t)(bl & 511) * 8192 + (size_t)t * 128;
            asm volatile("prefetch.global.L2 [%0];" :: "l"(wp));
        }
    }

    const float4* __restrict__ x4 =
        reinterpret_cast<const float4*>(x + ((size_t)b * SEQ + (size_t)c * SCHUNK) * DIM);

    float4 acc = make_float4(0.f, 0.f, 0.f, 0.f);
#pragma unroll 16
    for (int s = 0; s < SCHUNK; s++) {
        float4 v = __ldcs(&x4[(size_t)s * (DIM / 4) + t]);
        acc.x += v.x; acc.y += v.y; acc.z += v.z; acc.w += v.w;
    }
    reinterpret_cast<float4*>(g_partials)[((size_t)c * BATCH + b) * (DIM / 4) + t] = acc;
}

// ---------------------------------------------------------------------------
// Device-wide barrier for K2 (all FB2 blocks co-resident by launch bounds).
// ---------------------------------------------------------------------------
__device__ __forceinline__ void grid_barrier(int which) {
    __syncthreads();
    if (threadIdx.x == 0) {
        __threadfence();
        atomicAdd((unsigned*)&g_bar[which], 1u);
        while (g_bar[which] < FB2) { }
        __threadfence();
    }
    __syncthreads();
}

// ---------------------------------------------------------------------------
// K2: fused tail. grid 512, block 256 (8 warps), 4 CTAs/SM.
//  (R)  blocks 0..127: reduce 64 chunk-partials -> mean (batch b=bid>>3,
//       32-f4 column group q=bid&7).
//  bar -> (G1) blocks 0..511: enc = m @ Wenc^T + benc.
//       hg=bid>>2 (8 h each), qb=bid&3 (4 batches); warp = 1 h x 4 batches,
//       full K=1024 as 8 reg float4 W loads (L2-hot from K1's prefetch).
//  bar -> (G2) same shape for out = enc @ Wout^T + bout.
// Self-resetting barriers => graph-replay safe; all sums fixed-order.
// ---------------------------------------------------------------------------
__global__ void __launch_bounds__(256, 4)
fused_tail_kernel(const float* __restrict__ Wenc,
                  const float* __restrict__ benc,
                  const float* __restrict__ Wout,
                  const float* __restrict__ bout,
                  float* __restrict__ dout) {
    __shared__ float4 smA[4 * (DIM / 4)];   // 16 KB

    const int t    = threadIdx.x;
    const int w    = t >> 5;
    const int lane = t & 31;
    const int bid  = blockIdx.x;

    // ---- (R) reduce ----
    if (bid < 128) {
        const int b   = bid >> 3;
        const int q   = bid & 7;
        const int col = t & 31;
        const int cg  = t >> 5;            // 8 chunk-groups of 8
        const float4* __restrict__ p4 = reinterpret_cast<const float4*>(g_partials);

        float4 acc = make_float4(0.f, 0.f, 0.f, 0.f);
#pragma unroll
        for (int i = 0; i < 8; i++) {
            const int c = cg * 8 + i;      // chunk 0..63
            float4 v = p4[((size_t)c * BATCH + b) * (DIM / 4) + q * 32 + col];
            acc.x += v.x; acc.y += v.y; acc.z += v.z; acc.w += v.w;
        }
        smA[t] = acc;
        __syncthreads();
        if (t < 32) {
            float4 r = make_float4(0.f, 0.f, 0.f, 0.f);
#pragma unroll
            for (int g = 0; g < 8; g++) {
                float4 v = smA[t + g * 32];
                r.x += v.x; r.y += v.y; r.z += v.z; r.w += v.w;
            }
            const float inv = 1.0f / (float)SEQ;
            r.x *= inv; r.y *= inv; r.z *= inv; r.w *= inv;
            reinterpret_cast<float4*>(g_m)[(size_t)b * (DIM / 4) + q * 32 + t] = r;
        }
        __syncthreads();
    }

    grid_barrier(0);

    const int hg = bid >> 2;
    const int qb = bid & 3;
    const int h  = hg * 8 + w;

    // ---- (G1) enc = m @ Wenc^T + benc ----
    {
        const float4* __restrict__ M4 = reinterpret_cast<const float4*>(g_m);
#pragma unroll
        for (int i = 0; i < 4; i++)
            smA[t + i * 256] = M4[(size_t)qb * 1024 + t + i * 256];
        __syncthreads();

        const float4* __restrict__ W4 = reinterpret_cast<const float4*>(Wenc) + (size_t)h * (DIM / 4);
        float4 wr[8];
#pragma unroll
        for (int i = 0; i < 8; i++)
            wr[i] = W4[lane + i * 32];

        float acc[4] = {0.f, 0.f, 0.f, 0.f};
#pragma unroll
        for (int i = 0; i < 8; i++) {
            const int j = lane + i * 32;
#pragma unroll
            for (int b = 0; b < 4; b++) {
                const float4 a = smA[b * 256 + j];
                acc[b] += wr[i].x * a.x + wr[i].y * a.y + wr[i].z * a.z + wr[i].w * a.w;
            }
        }
#pragma unroll
        for (int off = 16; off > 0; off >>= 1)
#pragma unroll
            for (int b = 0; b < 4; b++)
                acc[b] += __shfl_down_sync(0xffffffffu, acc[b], off);
        if (lane == 0) {
            const float bv = benc[h];
#pragma unroll
            for (int b = 0; b < 4; b++)
                g_enc[(size_t)(qb * 4 + b) * DIM + h] = acc[b] + bv;
        }
        __syncthreads();
    }

    grid_barrier(1);

    // ---- (G2) out = enc @ Wout^T + bout ----
    {
        const float4* __restrict__ E4 = reinterpret_cast<const float4*>(g_enc);
#pragma unroll
        for (int i = 0; i < 4; i++)
            smA[t + i * 256] = E4[(size_t)qb * 1024 + t + i * 256];
        __syncthreads();

        const float4* __restrict__ W4 = reinterpret_cast<const float4*>(Wout) + (size_t)h * (DIM / 4);
        float4 wr[8];
#pragma unroll
        for (int i = 0; i < 8; i++)
            wr[i] = W4[lane + i * 32];

        float acc[4] = {0.f, 0.f, 0.f, 0.f};
#pragma unroll
        for (int i = 0; i < 8; i++) {
            const int j = lane + i * 32;
#pragma unroll
            for (int b = 0; b < 4; b++) {
                const float4 a = smA[b * 256 + j];
                acc[b] += wr[i].x * a.x + wr[i].y * a.y + wr[i].z * a.z + wr[i].w * a.w;
            }
        }
#pragma unroll
        for (int off = 16; off > 0; off >>= 1)
#pragma unroll
            for (int b = 0; b < 4; b++)
                acc[b] += __shfl_down_sync(0xffffffffu, acc[b], off);
        if (lane == 0) {
            const float bv = bout[h];
#pragma unroll
            for (int b = 0; b < 4; b++)
                dout[(size_t)(qb * 4 + b) * DIM + h] = acc[b] + bv;
        }
    }

    // ---- reset counters for next graph replay (last block out). ----
    __syncthreads();
    if (t == 0) {
        unsigned old = atomicAdd(&g_exit, 1u);
        if (old == FB2 - 1) {
            g_bar[0] = 0;
            g_bar[1] = 0;
            __threadfence();
            g_exit = 0;
        }
    }
}

extern "C" void kernel_launch(void* const* d_in, const int* in_sizes, int n_in,
                              void* d_out, int out_size) {
    const float* x     = (const float*)d_in[0];
    const float* W_enc = (const float*)d_in[1];
    const float* b_enc = (const float*)d_in[2];
    const float* W_out = (const float*)d_in[3];
    const float* b_out = (const float*)d_in[4];
    float* out = (float*)d_out;

    (void)in_sizes; (void)n_in; (void)out_size;

    mean_partial_kernel<<<dim3(BATCH, NCHUNK), 256>>>(x, W_enc, W_out);
    fused_tail_kernel<<<FB2, 256>>>(W_enc, b_enc, W_out, b_out, out);
}

// round 9
// speedup vs baseline: 1.0479x; 1.0078x over previous
#include <cuda_runtime.h>

// HCEN forward, two kernels:
//  K1: x partial-sum stream (proven ~7.1 TB/s shape, untouched).
//  K2: fused tail (reduce -> GEMM1 -> GEMM2), 128 blocks (1/SM, co-resident),
//      warp = 1 h-row x 16 batches (two 8-batch halves) so W is read ONCE.
//      Wenc -> registers at kernel start (latency hidden under reduce);
//      Wout -> L2 prefetch at kernel start (~4us lead, survives).

#define BATCH 16
#define SEQ   4096
#define DIM   1024
#define NCHUNK 64
#define SCHUNK (SEQ / NCHUNK)   // 64
#define FB2   128               // tail grid (1 block/SM, co-resident)

// Device-global scratch (no allocation allowed).
__device__ float g_partials[NCHUNK * BATCH * DIM];   // 4 MB
__device__ float g_m[BATCH * DIM];                   // 64 KB
__device__ float g_enc[BATCH * DIM];                 // 64 KB
__device__ volatile unsigned g_bar[2];               // zero-init; self-resetting
__device__ unsigned g_exit;

// ---------------------------------------------------------------------------
// K1: partial sums over S-chunks. grid (16, 64), block 256.
// Fully coalesced float4 loads, __ldcs (read-once, evict-first).
// ---------------------------------------------------------------------------
__global__ void mean_partial_kernel(const float* __restrict__ x) {
    const int b = blockIdx.x;
    const int c = blockIdx.y;
    const int t = threadIdx.x;

    const float4* __restrict__ x4 =
        reinterpret_cast<const float4*>(x + ((size_t)b * SEQ + (size_t)c * SCHUNK) * DIM);

    float4 acc = make_float4(0.f, 0.f, 0.f, 0.f);
#pragma unroll 16
    for (int s = 0; s < SCHUNK; s++) {
        float4 v = __ldcs(&x4[(size_t)s * (DIM / 4) + t]);
        acc.x += v.x; acc.y += v.y; acc.z += v.z; acc.w += v.w;
    }
    reinterpret_cast<float4*>(g_partials)[((size_t)c * BATCH + b) * (DIM / 4) + t] = acc;
}

// ---------------------------------------------------------------------------
// Device-wide barrier for K2 (128 blocks always co-resident).
// ---------------------------------------------------------------------------
__device__ __forceinline__ void grid_barrier(int which) {
    __syncthreads();
    if (threadIdx.x == 0) {
        __threadfence();
        atomicAdd((unsigned*)&g_bar[which], 1u);
        while (g_bar[which] < FB2) { }
        __threadfence();
    }
    __syncthreads();
}

// ---------------------------------------------------------------------------
// K2: fused tail. grid 128, block 256 (8 warps). Warp w owns h = bid*8 + w.
//  start: Wenc row -> 8 reg float4 (drains under reduce);
//         Wout slice -> prefetch.global.L2 (32 KB/block, 4 MB total).
//  (R)   reduce 64 chunk-partials -> mean (batch bid>>3, col group bid&7).
//  bar -> (G1) enc = m @ Wenc^T + benc   (two 8-batch halves, 32 KB smem A).
//  bar -> (G2) out = enc @ Wout^T + bout (W from L2).
// Self-resetting barriers => graph-replay safe; all sums fixed-order.
// ---------------------------------------------------------------------------
__global__ void fused_tail_kernel(const float* __restrict__ Wenc,
                                  const float* __restrict__ benc,
                                  const float* __restrict__ Wout,
                                  const float* __restrict__ bout,
                                  float* __restrict__ dout) {
    __shared__ float4 smA[8 * (DIM / 4)];   // 32 KB (A tile; reduce scratch)

    const int t    = threadIdx.x;
    const int w    = t >> 5;
    const int lane = t & 31;
    const int bid  = blockIdx.x;
    const int h    = bid * 8 + w;

    // ---- Wenc row into registers (independent; overlaps the reduce). ----
    const float4* __restrict__ We4 =
        reinterpret_cast<const float4*>(Wenc) + (size_t)h * (DIM / 4);
    float4 wr[8];
#pragma unroll
    for (int i = 0; i < 8; i++)
        wr[i] = We4[lane + i * 32];

    // ---- Wout slice -> L2 (32 KB per block; consumed ~4us later). ----
    {
        const char* wp = reinterpret_cast<const char*>(Wout) +
                         (size_t)bid * 32768 + (size_t)t * 128;
        asm volatile("prefetch.global.L2 [%0];" :: "l"(wp));
    }

    // ---- (R) reduce 64 chunk-partials -> mean. ----
    {
        const int b   = bid >> 3;          // batch
        const int q   = bid & 7;           // 32-f4 column group
        const int col = t & 31;
        const int cg  = t >> 5;            // 8 chunk-groups of 8
        const float4* __restrict__ p4 = reinterpret_cast<const float4*>(g_partials);

        float4 acc = make_float4(0.f, 0.f, 0.f, 0.f);
#pragma unroll
        for (int i = 0; i < 8; i++) {
            const int c = cg * 8 + i;
            float4 v = p4[((size_t)c * BATCH + b) * (DIM / 4) + q * 32 + col];
            acc.x += v.x; acc.y += v.y; acc.z += v.z; acc.w += v.w;
        }
        smA[t] = acc;
        __syncthreads();
        if (t < 32) {
            float4 r = make_float4(0.f, 0.f, 0.f, 0.f);
#pragma unroll
            for (int g = 0; g < 8; g++) {
                float4 v = smA[t + g * 32];
                r.x += v.x; r.y += v.y; r.z += v.z; r.w += v.w;
            }
            const float inv = 1.0f / (float)SEQ;
            r.x *= inv; r.y *= inv; r.z *= inv; r.w *= inv;
            reinterpret_cast<float4*>(g_m)[(size_t)b * (DIM / 4) + q * 32 + t] = r;
        }
        __syncthreads();
    }

    grid_barrier(0);

    // ---- (G1) enc = m @ Wenc^T + benc.  Warp: 1 h x 16 b (two halves). ----
    {
        const float4* __restrict__ M4 = reinterpret_cast<const float4*>(g_m);
        const float bv = benc[h];
#pragma unroll
        for (int half = 0; half < 2; half++) {
#pragma unroll
            for (int i = 0; i < 8; i++)
                smA[t + i * 256] = M4[(size_t)half * 2048 + t + i * 256];
            __syncthreads();

            float acc[8] = {0.f, 0.f, 0.f, 0.f, 0.f, 0.f, 0.f, 0.f};
#pragma unroll
            for (int i = 0; i < 8; i++) {
                const int j = lane + i * 32;
#pragma unroll
                for (int b = 0; b < 8; b++) {
                    const float4 a = smA[b * 256 + j];
                    acc[b] += wr[i].x * a.x + wr[i].y * a.y + wr[i].z * a.z + wr[i].w * a.w;
                }
            }
#pragma unroll
            for (int off = 16; off > 0; off >>= 1)
#pragma unroll
                for (int b = 0; b < 8; b++)
                    acc[b] += __shfl_down_sync(0xffffffffu, acc[b], off);
            if (lane == 0) {
#pragma unroll
                for (int b = 0; b < 8; b++)
                    g_enc[(size_t)(half * 8 + b) * DIM + h] = acc[b] + bv;
            }
            __syncthreads();
        }
    }

    grid_barrier(1);

    // ---- (G2) out = enc @ Wout^T + bout.  W from L2 (prefetched). ----
    {
        const float4* __restrict__ Wo4 =
            reinterpret_cast<const float4*>(Wout) + (size_t)h * (DIM / 4);
        float4 wo[8];
#pragma unroll
        for (int i = 0; i < 8; i++)
            wo[i] = Wo4[lane + i * 32];

        const float4* __restrict__ E4 = reinterpret_cast<const float4*>(g_enc);
        const float bv = bout[h];
#pragma unroll
        for (int half = 0; half < 2; half++) {
#pragma unroll
            for (int i = 0; i < 8; i++)
                smA[t + i * 256] = E4[(size_t)half * 2048 + t + i * 256];
            __syncthreads();

            float acc[8] = {0.f, 0.f, 0.f, 0.f, 0.f, 0.f, 0.f, 0.f};
#pragma unroll
            for (int i = 0; i < 8; i++) {
                const int j = lane + i * 32;
#pragma unroll
                for (int b = 0; b < 8; b++) {
                    const float4 a = smA[b * 256 + j];
                    acc[b] += wo[i].x * a.x + wo[i].y * a.y + wo[i].z * a.z + wo[i].w * a.w;
                }
            }
#pragma unroll
            for (int off = 16; off > 0; off >>= 1)
#pragma unroll
                for (int b = 0; b < 8; b++)
                    acc[b] += __shfl_down_sync(0xffffffffu, acc[b], off);
            if (lane == 0) {
#pragma unroll
                for (int b = 0; b < 8; b++)
                    dout[(size_t)(half * 8 + b) * DIM + h] = acc[b] + bv;
            }
            __syncthreads();
        }
    }

    // ---- reset counters for next graph replay (last block out). ----
    if (t == 0) {
        unsigned old = atomicAdd(&g_exit, 1u);
        if (old == FB2 - 1) {
            g_bar[0] = 0;
            g_bar[1] = 0;
            __threadfence();
            g_exit = 0;
        }
    }
}

extern "C" void kernel_launch(void* const* d_in, const int* in_sizes, int n_in,
                              void* d_out, int out_size) {
    const float* x     = (const float*)d_in[0];
    const float* W_enc = (const float*)d_in[1];
    const float* b_enc = (const float*)d_in[2];
    const float* W_out = (const float*)d_in[3];
    const float* b_out = (const float*)d_in[4];
    float* out = (float*)d_out;

    (void)in_sizes; (void)n_in; (void)out_size;

    mean_partial_kernel<<<dim3(BATCH, NCHUNK), 256>>>(x);
    fused_tail_kernel<<<FB2, 256>>>(W_enc, b_enc, W_out, b_out, out);
}

// round 10
// speedup vs baseline: 1.0724x; 1.0234x over previous
#include <cuda_runtime.h>

// HCEN forward, two kernels:
//  K1: x stream (proven shape) accumulating the batch-sums DIRECTLY into g_m
//      via atomicAdd (red.global) -> no partials array, no reduce phase.
//  K2: 128 blocks (1/SM, co-resident). Loads BOTH W rows into registers as
//      one front-loaded DRAM burst (MLP=16/thread), then G1 -> barrier ->
//      (zero g_m for next replay) -> G2. Single barrier, no mid-kernel DRAM.

#define BATCH 16
#define SEQ   4096
#define DIM   1024
#define NCHUNK 64
#define SCHUNK (SEQ / NCHUNK)   // 64
#define FB2   128               // tail grid (1 block/SM, co-resident)

// Device-global scratch (no allocation allowed).
__device__ float g_m[BATCH * DIM];       // 64 KB (sum accumulator; K2 re-zeroes)
__device__ float g_enc[BATCH * DIM];     // 64 KB
__device__ volatile unsigned g_bar[1];   // zero-init; self-resetting
__device__ unsigned g_exit;

// ---------------------------------------------------------------------------
// K1: grid (16, 64), block 256. Block (b,c) sums rows [c*64, c*64+64) of
// batch b; thread t owns float4 column t. __ldcs: read-once, evict-first.
// Result contributed to g_m[b] via 4 atomicAdds per thread (red.global.f32;
// 64 contributors per address, spread over the 36us stream -> negligible).
// ---------------------------------------------------------------------------
__global__ void mean_partial_kernel(const float* __restrict__ x) {
    const int b = blockIdx.x;
    const int c = blockIdx.y;
    const int t = threadIdx.x;

    const float4* __restrict__ x4 =
        reinterpret_cast<const float4*>(x + ((size_t)b * SEQ + (size_t)c * SCHUNK) * DIM);

    float4 acc = make_float4(0.f, 0.f, 0.f, 0.f);
#pragma unroll 16
    for (int s = 0; s < SCHUNK; s++) {
        float4 v = __ldcs(&x4[(size_t)s * (DIM / 4) + t]);
        acc.x += v.x; acc.y += v.y; acc.z += v.z; acc.w += v.w;
    }

    float* gm = g_m + (size_t)b * DIM + (size_t)t * 4;
    atomicAdd(gm + 0, acc.x);
    atomicAdd(gm + 1, acc.y);
    atomicAdd(gm + 2, acc.z);
    atomicAdd(gm + 3, acc.w);
}

// ---------------------------------------------------------------------------
// Device-wide barrier for K2 (128 blocks always co-resident).
// ---------------------------------------------------------------------------
__device__ __forceinline__ void grid_barrier(int which) {
    __syncthreads();
    if (threadIdx.x == 0) {
        __threadfence();
        atomicAdd((unsigned*)&g_bar[which], 1u);
        while (g_bar[which] < FB2) { }
        __threadfence();
    }
    __syncthreads();
}

// ---------------------------------------------------------------------------
// K2: fused GEMM tail. grid 128, block 256 (8 warps). Warp w owns
// h = bid*8 + w for the FULL pipeline (both layers, all 16 batches).
//  start: Wenc row -> wr[8] regs, Wout row -> wo[8] regs (one 8 MB burst).
//  (G1) enc = (sum/SEQ) @ Wenc^T + benc  (two 8-batch halves via 32 KB smem)
//  barrier -> zero own g_m slice (replay reset) ->
//  (G2) out = enc @ Wout^T + bout.
// ---------------------------------------------------------------------------
__global__ void fused_tail_kernel(const float* __restrict__ Wenc,
                                  const float* __restrict__ benc,
                                  const float* __restrict__ Wout,
                                  const float* __restrict__ bout,
                                  float* __restrict__ dout) {
    __shared__ float4 smA[8 * (DIM / 4)];   // 32 KB A tile

    const int t    = threadIdx.x;
    const int w    = t >> 5;
    const int lane = t & 31;
    const int bid  = blockIdx.x;
    const int h    = bid * 8 + w;

    // ---- Front-loaded DRAM burst: both W rows into registers. ----
    const float4* __restrict__ We4 =
        reinterpret_cast<const float4*>(Wenc) + (size_t)h * (DIM / 4);
    const float4* __restrict__ Wo4 =
        reinterpret_cast<const float4*>(Wout) + (size_t)h * (DIM / 4);
    float4 wr[8], wo[8];
#pragma unroll
    for (int i = 0; i < 8; i++) wr[i] = We4[lane + i * 32];
#pragma unroll
    for (int i = 0; i < 8; i++) wo[i] = Wo4[lane + i * 32];

    // ---- (G1) enc = (g_m / SEQ) @ Wenc^T + benc ----
    {
        const float4* __restrict__ M4 = reinterpret_cast<const float4*>(g_m);
        const float bv  = benc[h];
        const float inv = 1.0f / (float)SEQ;
#pragma unroll
        for (int half = 0; half < 2; half++) {
#pragma unroll
            for (int i = 0; i < 8; i++) {
                float4 v = M4[(size_t)half * 2048 + t + i * 256];
                v.x *= inv; v.y *= inv; v.z *= inv; v.w *= inv;
                smA[t + i * 256] = v;
            }
            __syncthreads();

            float acc[8] = {0.f, 0.f, 0.f, 0.f, 0.f, 0.f, 0.f, 0.f};
#pragma unroll
            for (int i = 0; i < 8; i++) {
                const int j = lane + i * 32;
#pragma unroll
                for (int b = 0; b < 8; b++) {
                    const float4 a = smA[b * 256 + j];
                    acc[b] += wr[i].x * a.x + wr[i].y * a.y + wr[i].z * a.z + wr[i].w * a.w;
                }
            }
#pragma unroll
            for (int off = 16; off > 0; off >>= 1)
#pragma unroll
                for (int b = 0; b < 8; b++)
                    acc[b] += __shfl_down_sync(0xffffffffu, acc[b], off);
            if (lane == 0) {
#pragma unroll
                for (int b = 0; b < 8; b++)
                    g_enc[(size_t)(half * 8 + b) * DIM + h] = acc[b] + bv;
            }
            __syncthreads();
        }
    }

    grid_barrier(0);

    // ---- Reset own g_m slice for the next graph replay. ----
    // 16384 floats / 128 blocks = 128 floats per block.
    if (t < 128)
        g_m[(size_t)bid * 128 + t] = 0.f;

    // ---- (G2) out = enc @ Wout^T + bout ----
    {
        const float4* __restrict__ E4 = reinterpret_cast<const float4*>(g_enc);
        const float bv = bout[h];
#pragma unroll
        for (int half = 0; half < 2; half++) {
#pragma unroll
            for (int i = 0; i < 8; i++)
                smA[t + i * 256] = E4[(size_t)half * 2048 + t + i * 256];
            __syncthreads();

            float acc[8] = {0.f, 0.f, 0.f, 0.f, 0.f, 0.f, 0.f, 0.f};
#pragma unroll
            for (int i = 0; i < 8; i++) {
                const int j = lane + i * 32;
#pragma unroll
                for (int b = 0; b < 8; b++) {
                    const float4 a = smA[b * 256 + j];
                    acc[b] += wo[i].x * a.x + wo[i].y * a.y + wo[i].z * a.z + wo[i].w * a.w;
                }
            }
#pragma unroll
            for (int off = 16; off > 0; off >>= 1)
#pragma unroll
                for (int b = 0; b < 8; b++)
                    acc[b] += __shfl_down_sync(0xffffffffu, acc[b], off);
            if (lane == 0) {
#pragma unroll
                for (int b = 0; b < 8; b++)
                    dout[(size_t)(half * 8 + b) * DIM + h] = acc[b] + bv;
            }
            __syncthreads();
        }
    }

    // ---- reset barrier counters (last block out). ----
    if (t == 0) {
        unsigned old = atomicAdd(&g_exit, 1u);
        if (old == FB2 - 1) {
            g_bar[0] = 0;
            __threadfence();
            g_exit = 0;
        }
    }
}

extern "C" void kernel_launch(void* const* d_in, const int* in_sizes, int n_in,
                              void* d_out, int out_size) {
    const float* x     = (const float*)d_in[0];
    const float* W_enc = (const float*)d_in[1];
    const float* b_enc = (const float*)d_in[2];
    const float* W_out = (const float*)d_in[3];
    const float* b_out = (const float*)d_in[4];
    float* out = (float*)d_out;

    (void)in_sizes; (void)n_in; (void)out_size;

    mean_partial_kernel<<<dim3(BATCH, NCHUNK), 256>>>(x);
    fused_tail_kernel<<<FB2, 256>>>(W_enc, b_enc, W_out, b_out, out);
}

// round 12
// speedup vs baseline: 1.0786x; 1.0057x over previous
#include <cuda_runtime.h>

// HCEN forward, two kernels (capture-safe: default stream, launches only):
//  K1: x stream (proven shape), accumulating batch sums into g_m via
//      atomicAdd -> no partials array, no reduce phase.
//  K2: fused GEMM tail, 256 blocks @ 2/SM guaranteed co-resident
//      (__launch_bounds__(256,2)) -> safe single grid barrier, and 2x the
//      parallelism of R10's 128-block tail in every phase. Each h-row is
//      computed by 2 blocks (one per 8-batch half); W rows land in registers
//      as a front-loaded burst (2nd block hits L2).

#define BATCH 16
#define SEQ   4096
#define DIM   1024
#define NCHUNK 64
#define SCHUNK (SEQ / NCHUNK)   // 64
#define FB2   256               // tail grid (2 blocks/SM, co-resident)

// Device-global scratch (no allocation allowed).
__device__ float g_m[BATCH * DIM];       // 64 KB (sum accumulator; K2 re-zeroes)
__device__ float g_enc[BATCH * DIM];     // 64 KB
__device__ volatile unsigned g_bar[1];   // zero-init; self-resetting
__device__ unsigned g_exit;

// ---------------------------------------------------------------------------
// K1: grid (16, 64), block 256. Block (b,c) sums rows [c*64, c*64+64) of
// batch b; thread t owns float4 column t. __ldcs: read-once, evict-first.
// Contributes to g_m[b] via 4 red.global.f32 per thread (64 contributors per
// address spread over the 36us stream -> negligible serialization).
// ---------------------------------------------------------------------------
__global__ void mean_partial_kernel(const float* __restrict__ x) {
    const int b = blockIdx.x;
    const int c = blockIdx.y;
    const int t = threadIdx.x;

    const float4* __restrict__ x4 =
        reinterpret_cast<const float4*>(x + ((size_t)b * SEQ + (size_t)c * SCHUNK) * DIM);

    float4 acc = make_float4(0.f, 0.f, 0.f, 0.f);
#pragma unroll 16
    for (int s = 0; s < SCHUNK; s++) {
        float4 v = __ldcs(&x4[(size_t)s * (DIM / 4) + t]);
        acc.x += v.x; acc.y += v.y; acc.z += v.z; acc.w += v.w;
    }

    float* gm = g_m + (size_t)b * DIM + (size_t)t * 4;
    atomicAdd(gm + 0, acc.x);
    atomicAdd(gm + 1, acc.y);
    atomicAdd(gm + 2, acc.z);
    atomicAdd(gm + 3, acc.w);
}

// ---------------------------------------------------------------------------
// Grid barrier across K2's 256 co-resident blocks.
// ---------------------------------------------------------------------------
__device__ __forceinline__ void grid_barrier(int which) {
    __syncthreads();
    if (threadIdx.x == 0) {
        __threadfence();
        atomicAdd((unsigned*)&g_bar[which], 1u);
        while (g_bar[which] < FB2) { }
        __threadfence();
    }
    __syncthreads();
}

// ---------------------------------------------------------------------------
// K2: fused GEMM tail. grid 256, block 256 (8 warps), 2 CTAs/SM.
// Block bid: h-group hg = bid>>1 (8 h rows), batch half = bid&1 (8 batches).
// Warp w owns h = hg*8 + w for its half.
//  start: Wenc row -> wr[8] regs, Wout row -> wo[8] regs (front burst).
//  (G1) enc[half] = (g_m[half]/SEQ) @ Wenc^T + benc   (8 KB... 32KB smem A)
//  barrier -> zero own g_m slice (replay reset) ->
//  (G2) out[half] = enc[half] @ Wout^T + bout.
// ---------------------------------------------------------------------------
__global__ void __launch_bounds__(256, 2)
fused_tail_kernel(const float* __restrict__ Wenc,
                  const float* __restrict__ benc,
                  const float* __restrict__ Wout,
                  const float* __restrict__ bout,
                  float* __restrict__ dout) {
    __shared__ float4 smA[8 * (DIM / 4)];   // 32 KB: 8 batches x full K

    const int t    = threadIdx.x;
    const int w    = t >> 5;
    const int lane = t & 31;
    const int bid  = blockIdx.x;
    const int hg   = bid >> 1;
    const int half = bid & 1;
    const int h    = hg * 8 + w;

    // ---- Front-loaded W burst into registers. ----
    const float4* __restrict__ We4 =
        reinterpret_cast<const float4*>(Wenc) + (size_t)h * (DIM / 4);
    const float4* __restrict__ Wo4 =
        reinterpret_cast<const float4*>(Wout) + (size_t)h * (DIM / 4);
    float4 wr[8], wo[8];
#pragma unroll
    for (int i = 0; i < 8; i++) wr[i] = We4[lane + i * 32];
#pragma unroll
    for (int i = 0; i < 8; i++) wo[i] = Wo4[lane + i * 32];

    // ---- (G1) enc = (g_m / SEQ) @ Wenc^T + benc, this block's 8 batches. ----
    {
        const float4* __restrict__ M4 = reinterpret_cast<const float4*>(g_m);
        const float inv = 1.0f / (float)SEQ;
#pragma unroll
        for (int i = 0; i < 8; i++) {
            float4 v = M4[(size_t)half * 2048 + t + i * 256];
            v.x *= inv; v.y *= inv; v.z *= inv; v.w *= inv;
            smA[t + i * 256] = v;
        }
        __syncthreads();

        float acc[8] = {0.f, 0.f, 0.f, 0.f, 0.f, 0.f, 0.f, 0.f};
#pragma unroll
        for (int i = 0; i < 8; i++) {
            const int j = lane + i * 32;
#pragma unroll
            for (int b = 0; b < 8; b++) {
                const float4 a = smA[b * 256 + j];
                acc[b] += wr[i].x * a.x + wr[i].y * a.y + wr[i].z * a.z + wr[i].w * a.w;
            }
        }
#pragma unroll
        for (int off = 16; off > 0; off >>= 1)
#pragma unroll
            for (int b = 0; b < 8; b++)
                acc[b] += __shfl_down_sync(0xffffffffu, acc[b], off);
        if (lane == 0) {
            const float bv = benc[h];
#pragma unroll
            for (int b = 0; b < 8; b++)
                g_enc[(size_t)(half * 8 + b) * DIM + h] = acc[b] + bv;
        }
        __syncthreads();
    }

    grid_barrier(0);

    // ---- Reset own g_m slice for next graph replay (64 floats/block). ----
    if (t < 64)
        g_m[(size_t)bid * 64 + t] = 0.f;

    // ---- (G2) out = enc @ Wout^T + bout, this block's 8 batches. ----
    {
        const float4* __restrict__ E4 = reinterpret_cast<const float4*>(g_enc);
#pragma unroll
        for (int i = 0; i < 8; i++)
            smA[t + i * 256] = E4[(size_t)half * 2048 + t + i * 256];
        __syncthreads();

        float acc[8] = {0.f, 0.f, 0.f, 0.f, 0.f, 0.f, 0.f, 0.f};
#pragma unroll
        for (int i = 0; i < 8; i++) {
            const int j = lane + i * 32;
#pragma unroll
            for (int b = 0; b < 8; b++) {
                const float4 a = smA[b * 256 + j];
                acc[b] += wo[i].x * a.x + wo[i].y * a.y + wo[i].z * a.z + wo[i].w * a.w;
            }
        }
#pragma unroll
        for (int off = 16; off > 0; off >>= 1)
#pragma unroll
            for (int b = 0; b < 8; b++)
                acc[b] += __shfl_down_sync(0xffffffffu, acc[b], off);
        if (lane == 0) {
            const float bv = bout[h];
#pragma unroll
            for (int b = 0; b < 8; b++)
                dout[(size_t)(half * 8 + b) * DIM + h] = acc[b] + bv;
        }
    }

    // ---- reset counters for next graph replay (last block out). ----
    __syncthreads();
    if (t == 0) {
        unsigned old = atomicAdd(&g_exit, 1u);
        if (old == FB2 - 1) {
            g_bar[0] = 0;
            __threadfence();
            g_exit = 0;
        }
    }
}

extern "C" void kernel_launch(void* const* d_in, const int* in_sizes, int n_in,
                              void* d_out, int out_size) {
    const float* x     = (const float*)d_in[0];
    const float* W_enc = (const float*)d_in[1];
    const float* b_enc = (const float*)d_in[2];
    const float* W_out = (const float*)d_in[3];
    const float* b_out = (const float*)d_in[4];
    float* out = (float*)d_out;

    (void)in_sizes; (void)n_in; (void)out_size;

    mean_partial_kernel<<<dim3(BATCH, NCHUNK), 256>>>(x);
    fused_tail_kernel<<<FB2, 256>>>(W_enc, b_enc, W_out, b_out, out);
}